// round 9
// baseline (speedup 1.0000x reference)
#include <cuda_runtime.h>
#include <math.h>

#define SS        7
#define NPROP     32
#define NCH       128
#define CPB       4               // channels per block
#define FD        32
#define FH        64
#define FW        64
#define CHVOL     (FD * FH * FW)
#define LMAX      18              // max crop extent per dim
#define NROWMAX   (LMAX * LMAX)   // 324
#define THREADS   512
#define RSTRIDE   73              // floor(512/7) row-slots in phase 1
#define NSLOT     10              // floor(512/49) z-slots in phases 2/3

__global__ __launch_bounds__(THREADS)
void crop_roi_kernel(const float* __restrict__ f,
                     const float* __restrict__ proposals,
                     float* __restrict__ out)
{
    __shared__ int   rowoff[NROWMAX];                   //  1296 B
    __shared__ float crop7[CPB][NROWMAX * SS];          // 36288 B  x-pooled
    __shared__ float tmpzy[CPB][LMAX * SS * SS];        // 14112 B  y-pooled

    const int n   = blockIdx.x;
    const int cg  = blockIdx.y;                         // c = cg*CPB + {0..3}
    const int tid = threadIdx.x;

    // ---- Phase 0: box geometry (redundant per thread) + rowoff table ----
    const float* p = proposals + n * 8;
    const int b = (int)p[0];

    int c0[3], L[3];
    const int dims[3] = {FD, FH, FW};
#pragma unroll
    for (int d = 0; d < 3; d++) {
        const float ctr = p[2 + d];
        const float sd  = p[5 + d];
        int lo = (int)floorf((ctr - 0.5f * sd) * 0.25f);
        int hi = (int)ceilf ((ctr + 0.5f * sd) * 0.25f);
        lo = max(lo, 0);
        hi = min(hi, dims[d]);
        c0[d] = lo;
        L[d]  = hi - lo;     // >= 4 (side >= 16)
    }
    const int Lz = L[0], Ly = L[1], Lx = L[2];
    const int nrows = Lz * Ly;                          // <= 324 < THREADS

    if (tid < nrows) {
        const int z = tid / Ly;                         // one runtime div, once
        const int y = tid - z * Ly;
        rowoff[tid] = ((c0[0] + z) * FH + (c0[1] + y)) * FW + c0[2];
    }

    const float* fb0 = f + ((size_t)b * NCH + cg * CPB) * (size_t)CHVOL;
    __syncthreads();

    // ---- Phase 1: x-pool gmem -> crop7[ch][r*7 + bx], 4 channels ----
    // Thread layout: tid = r0*7 + bx (x-window constant per thread).
    {
        const int bx = tid % SS;
        const int r0 = tid / SS;                        // 0..73
        const int x0 =  bx      * Lx / SS;
        const int x1 = ((bx + 1) * Lx + SS - 1) / SS;
        const int w  = x1 - x0;                         // 1..4, per-thread constant

        if (r0 < RSTRIDE) {
            for (int r = r0; r < nrows; r += RSTRIDE) {
                const int off = rowoff[r] + x0;
                float m[CPB];
#pragma unroll
                for (int ch = 0; ch < CPB; ch++)
                    m[ch] = __ldg(fb0 + (size_t)ch * CHVOL + off);
                if (w > 1) {
#pragma unroll
                    for (int ch = 0; ch < CPB; ch++)
                        m[ch] = fmaxf(m[ch], __ldg(fb0 + (size_t)ch * CHVOL + off + 1));
                }
                if (w > 2) {
#pragma unroll
                    for (int ch = 0; ch < CPB; ch++)
                        m[ch] = fmaxf(m[ch], __ldg(fb0 + (size_t)ch * CHVOL + off + 2));
                }
                if (w > 3) {
#pragma unroll
                    for (int ch = 0; ch < CPB; ch++)
                        m[ch] = fmaxf(m[ch], __ldg(fb0 + (size_t)ch * CHVOL + off + 3));
                }
#pragma unroll
                for (int ch = 0; ch < CPB; ch++)
                    crop7[ch][r * SS + bx] = m[ch];
            }
        }
    }
    __syncthreads();

    // ---- Phase 2: y-pool crop7 -> tmpzy[ch][z*49 + by*7 + bx] ----
    // Thread layout: tid = zslot*49 + rem; channel loop unrolled.
    {
        const int rem = tid % (SS * SS);                // by*7+bx, constant
        const int s0  = tid / (SS * SS);                // 0..10
        const int by  = rem / SS;
        const int bx  = rem - by * SS;
        const int y0  =  by      * Ly / SS;
        const int y1  = ((by + 1) * Ly + SS - 1) / SS;
        const int wy  = y1 - y0;                        // 1..4, constant

        if (s0 < NSLOT) {
            for (int zz = s0; zz < Lz; zz += NSLOT) {
                const int ibase = (zz * Ly + y0) * SS + bx;
                const int obase = zz * (SS * SS) + rem;
#pragma unroll
                for (int ch = 0; ch < CPB; ch++) {
                    const float* rp = &crop7[ch][ibase];
                    float m = rp[0];
                    if (wy > 1) m = fmaxf(m, rp[SS]);
                    if (wy > 2) m = fmaxf(m, rp[2 * SS]);
                    if (wy > 3) m = fmaxf(m, rp[3 * SS]);
                    tmpzy[ch][obase] = m;
                }
            }
        }
    }
    __syncthreads();

    // ---- Phase 3: z-pool tmpzy -> out; channel loop unrolled ----
    float* outp = out + ((size_t)n * NCH + cg * CPB) * (SS * SS * SS);
    {
        const int rem = tid % (SS * SS);
        const int bz  = tid / (SS * SS);                // 0..10, valid < 7
        if (bz < SS) {
            const int z0 =  bz      * Lz / SS;
            const int z1 = ((bz + 1) * Lz + SS - 1) / SS;
            const int wz = z1 - z0;                     // 1..4

            const int ibase = z0 * (SS * SS) + rem;
            const int obase = bz * (SS * SS) + rem;
#pragma unroll
            for (int ch = 0; ch < CPB; ch++) {
                const float* rp = &tmpzy[ch][ibase];
                float m = rp[0];
                if (wz > 1) m = fmaxf(m, rp[SS * SS]);
                if (wz > 2) m = fmaxf(m, rp[2 * SS * SS]);
                if (wz > 3) m = fmaxf(m, rp[3 * SS * SS]);
                outp[ch * (SS * SS * SS) + obase] = m;
            }
        }
    }
}

extern "C" void kernel_launch(void* const* d_in, const int* in_sizes, int n_in,
                              void* d_out, int out_size)
{
    const float* f         = (const float*)d_in[0];
    const float* proposals = (const float*)d_in[2];
    float* out = (float*)d_out;

    dim3 grid(NPROP, NCH / CPB);
    crop_roi_kernel<<<grid, THREADS>>>(f, proposals, out);
}

// round 10
// speedup vs baseline: 1.1554x; 1.1554x over previous
#include <cuda_runtime.h>
#include <math.h>

#define SS        7
#define NPROP     32
#define NCH       128
#define CPB       2               // channels per block (R9 showed 4 is past optimum)
#define FD        32
#define FH        64
#define FW        64
#define CHVOL     (FD * FH * FW)
#define LMAX      18              // max crop extent per dim
#define NROWMAX   (LMAX * LMAX)   // 324
#define THREADS   256
#define RSTRIDE   36              // floor(256/7) row-slots in phase 1
#define NSLOT     5               // floor(256/49) slots in phases 2/3

__global__ __launch_bounds__(THREADS, 8)
void crop_roi_kernel(const float* __restrict__ f,
                     const float* __restrict__ proposals,
                     float* __restrict__ out)
{
    __shared__ int   rowoff[NROWMAX];                   //  1296 B
    __shared__ float crop7[CPB][NROWMAX * SS];          // 18144 B  x-pooled
    __shared__ float tmpzy[CPB][LMAX * SS * SS];        //  7056 B  y-pooled

    const int n   = blockIdx.x;
    const int cg  = blockIdx.y;                         // c = cg*CPB + {0,1}
    const int tid = threadIdx.x;

    // ---- Phase 0: box geometry (redundant per thread) + rowoff table ----
    const float* p = proposals + n * 8;
    const int b = (int)p[0];

    int c0[3], L[3];
    const int dims[3] = {FD, FH, FW};
#pragma unroll
    for (int d = 0; d < 3; d++) {
        const float ctr = p[2 + d];
        const float sd  = p[5 + d];
        int lo = (int)floorf((ctr - 0.5f * sd) * 0.25f);
        int hi = (int)ceilf ((ctr + 0.5f * sd) * 0.25f);
        lo = max(lo, 0);
        hi = min(hi, dims[d]);
        c0[d] = lo;
        L[d]  = hi - lo;     // >= 4 (side >= 16)
    }
    const int Lz = L[0], Ly = L[1], Lx = L[2];
    const int nrows = Lz * Ly;                          // <= 324 (may exceed 256)

    for (int i = tid; i < nrows; i += THREADS) {
        const int z = i / Ly;                           // <=2 runtime divs, once
        const int y = i - z * Ly;
        rowoff[i] = ((c0[0] + z) * FH + (c0[1] + y)) * FW + c0[2];
    }

    const float* fb0 = f + ((size_t)b * NCH + cg * CPB) * (size_t)CHVOL;
    __syncthreads();

    // ---- Phase 1: x-pool gmem -> crop7[ch][r*7 + bx], both channels ----
    // Thread layout: tid = r0*7 + bx (x-window constant per thread).
    {
        const int bx = tid % SS;
        const int r0 = tid / SS;                        // 0..36
        const int x0 =  bx      * Lx / SS;
        const int x1 = ((bx + 1) * Lx + SS - 1) / SS;
        const int w  = x1 - x0;                         // 1..4, per-thread constant

        if (r0 < RSTRIDE) {
            for (int r = r0; r < nrows; r += RSTRIDE) {
                const float* rp0 = fb0 + rowoff[r] + x0;
                const float* rp1 = rp0 + CHVOL;
                // 8 independent loads in flight per iteration (proven sweet spot)
                float m0 = __ldg(rp0);
                float m1 = __ldg(rp1);
                if (w > 1) { m0 = fmaxf(m0, __ldg(rp0 + 1)); m1 = fmaxf(m1, __ldg(rp1 + 1)); }
                if (w > 2) { m0 = fmaxf(m0, __ldg(rp0 + 2)); m1 = fmaxf(m1, __ldg(rp1 + 2)); }
                if (w > 3) { m0 = fmaxf(m0, __ldg(rp0 + 3)); m1 = fmaxf(m1, __ldg(rp1 + 3)); }
                crop7[0][r * SS + bx] = m0;
                crop7[1][r * SS + bx] = m1;
            }
        }
    }
    __syncthreads();

    // ---- Phase 2: y-pool crop7 -> tmpzy[ch][z*49 + by*7 + bx] ----
    // Thread layout: tid = zslot*49 + rem; channel loop unrolled.
    {
        const int rem = tid % (SS * SS);                // by*7+bx, constant
        const int s0  = tid / (SS * SS);                // 0..5
        const int by  = rem / SS;
        const int bx  = rem - by * SS;
        const int y0  =  by      * Ly / SS;
        const int y1  = ((by + 1) * Ly + SS - 1) / SS;
        const int wy  = y1 - y0;                        // 1..4, constant

        if (s0 < NSLOT) {
            for (int zz = s0; zz < Lz; zz += NSLOT) {
                const int ibase = (zz * Ly + y0) * SS + bx;
                const int obase = zz * (SS * SS) + rem;
#pragma unroll
                for (int ch = 0; ch < CPB; ch++) {
                    const float* rp = &crop7[ch][ibase];
                    float m = rp[0];
                    if (wy > 1) m = fmaxf(m, rp[SS]);
                    if (wy > 2) m = fmaxf(m, rp[2 * SS]);
                    if (wy > 3) m = fmaxf(m, rp[3 * SS]);
                    tmpzy[ch][obase] = m;
                }
            }
        }
    }
    __syncthreads();

    // ---- Phase 3: z-pool tmpzy -> out; channel loop unrolled ----
    float* outp = out + ((size_t)n * NCH + cg * CPB) * (SS * SS * SS);
    {
        const int rem = tid % (SS * SS);
        const int s0  = tid / (SS * SS);                // 0..5
        if (s0 < NSLOT) {
            for (int bz = s0; bz < SS; bz += NSLOT) {
                const int z0 =  bz      * Lz / SS;
                const int z1 = ((bz + 1) * Lz + SS - 1) / SS;
                const int wz = z1 - z0;                 // 1..4

                const int ibase = z0 * (SS * SS) + rem;
                const int obase = bz * (SS * SS) + rem;
#pragma unroll
                for (int ch = 0; ch < CPB; ch++) {
                    const float* rp = &tmpzy[ch][ibase];
                    float m = rp[0];
                    if (wz > 1) m = fmaxf(m, rp[SS * SS]);
                    if (wz > 2) m = fmaxf(m, rp[2 * SS * SS]);
                    if (wz > 3) m = fmaxf(m, rp[3 * SS * SS]);
                    outp[ch * (SS * SS * SS) + obase] = m;
                }
            }
        }
    }
}

extern "C" void kernel_launch(void* const* d_in, const int* in_sizes, int n_in,
                              void* d_out, int out_size)
{
    const float* f         = (const float*)d_in[0];
    const float* proposals = (const float*)d_in[2];
    float* out = (float*)d_out;

    dim3 grid(NPROP, NCH / CPB);
    crop_roi_kernel<<<grid, THREADS>>>(f, proposals, out);
}

// round 11
// speedup vs baseline: 1.2939x; 1.1199x over previous
#include <cuda_runtime.h>
#include <math.h>

#define SS        7
#define NPROP     32
#define NCH       128
#define CPB       2               // channels per block
#define FD        32
#define FH        64
#define FW        64
#define CHVOL     (FD * FH * FW)
#define LMAX      18              // max crop extent per dim
#define NROWMAX   (LMAX * LMAX)   // 324
#define THREADS   256
#define RSTRIDE   36              // floor(256/7) row-slots in phase 1
#define NSLOT     5               // floor(256/49) slots in fused pool phase

__global__ __launch_bounds__(THREADS, 8)
void crop_roi_kernel(const float* __restrict__ f,
                     const float* __restrict__ proposals,
                     float* __restrict__ out)
{
    __shared__ int   rowoff[NROWMAX];                   //  1296 B
    __shared__ float crop7[CPB][NROWMAX * SS];          // 18144 B  x-pooled

    const int n   = blockIdx.x;
    const int cg  = blockIdx.y;                         // c = cg*CPB + {0,1}
    const int tid = threadIdx.x;

    // ---- Phase 0: box geometry (redundant per thread) + rowoff table ----
    const float* p = proposals + n * 8;
    const int b = (int)p[0];

    int c0[3], L[3];
    const int dims[3] = {FD, FH, FW};
#pragma unroll
    for (int d = 0; d < 3; d++) {
        const float ctr = p[2 + d];
        const float sd  = p[5 + d];
        int lo = (int)floorf((ctr - 0.5f * sd) * 0.25f);
        int hi = (int)ceilf ((ctr + 0.5f * sd) * 0.25f);
        lo = max(lo, 0);
        hi = min(hi, dims[d]);
        c0[d] = lo;
        L[d]  = hi - lo;     // >= 4 (side >= 16)
    }
    const int Lz = L[0], Ly = L[1], Lx = L[2];
    const int nrows = Lz * Ly;                          // <= 324

    for (int i = tid; i < nrows; i += THREADS) {
        const int z = i / Ly;                           // <=2 runtime divs, once
        const int y = i - z * Ly;
        rowoff[i] = ((c0[0] + z) * FH + (c0[1] + y)) * FW + c0[2];
    }

    const float* fb0 = f + ((size_t)b * NCH + cg * CPB) * (size_t)CHVOL;
    __syncthreads();

    // ---- Phase 1: x-pool gmem -> crop7[ch][r*7 + bx], both channels ----
    // Thread layout: tid = r0*7 + bx (x-window constant per thread).
    {
        const int bx = tid % SS;
        const int r0 = tid / SS;                        // 0..36
        const int x0 =  bx      * Lx / SS;
        const int x1 = ((bx + 1) * Lx + SS - 1) / SS;
        const int w  = x1 - x0;                         // 1..4, per-thread constant

        if (r0 < RSTRIDE) {
            for (int r = r0; r < nrows; r += RSTRIDE) {
                const float* rp0 = fb0 + rowoff[r] + x0;
                const float* rp1 = rp0 + CHVOL;
                // 8 independent loads in flight per iteration
                float m0 = __ldg(rp0);
                float m1 = __ldg(rp1);
                if (w > 1) { m0 = fmaxf(m0, __ldg(rp0 + 1)); m1 = fmaxf(m1, __ldg(rp1 + 1)); }
                if (w > 2) { m0 = fmaxf(m0, __ldg(rp0 + 2)); m1 = fmaxf(m1, __ldg(rp1 + 2)); }
                if (w > 3) { m0 = fmaxf(m0, __ldg(rp0 + 3)); m1 = fmaxf(m1, __ldg(rp1 + 3)); }
                crop7[0][r * SS + bx] = m0;
                crop7[1][r * SS + bx] = m1;
            }
        }
    }
    __syncthreads();

    // ---- Phase 2 (fused y+z pool): crop7 -> out directly ----
    // Thread layout: tid = s0*49 + rem, rem = by*7+bx constant per thread.
    // Loop over 14 (ch,bz) slots; each bin reads wy*wz (<=16, avg ~3) smem vals.
    float* outp = out + ((size_t)n * NCH + cg * CPB) * (SS * SS * SS);
    {
        const int rem = tid % (SS * SS);                // by*7+bx, constant
        const int s0  = tid / (SS * SS);                // 0..5
        const int by  = rem / SS;
        const int bx  = rem - by * SS;
        const int y0  =  by      * Ly / SS;
        const int y1  = ((by + 1) * Ly + SS - 1) / SS;
        const int wy  = y1 - y0;                        // 1..4, constant

        if (s0 < NSLOT) {
            // 14 tasks: s = ch*7 + bz
            for (int s = s0; s < CPB * SS; s += NSLOT) {
                const int ch = (s < SS) ? 0 : 1;
                const int bz = (s < SS) ? s : s - SS;
                const int z0 =  bz      * Lz / SS;
                const int z1 = ((bz + 1) * Lz + SS - 1) / SS;

                float m = -INFINITY;
                for (int zz = z0; zz < z1; zz++) {
                    const float* rp = &crop7[ch][(zz * Ly + y0) * SS + bx];
                    float my = rp[0];
                    if (wy > 1) my = fmaxf(my, rp[SS]);
                    if (wy > 2) my = fmaxf(my, rp[2 * SS]);
                    if (wy > 3) my = fmaxf(my, rp[3 * SS]);
                    m = fmaxf(m, my);
                }
                outp[ch * (SS * SS * SS) + bz * (SS * SS) + rem] = m;
            }
        }
    }
}

extern "C" void kernel_launch(void* const* d_in, const int* in_sizes, int n_in,
                              void* d_out, int out_size)
{
    const float* f         = (const float*)d_in[0];
    const float* proposals = (const float*)d_in[2];
    float* out = (float*)d_out;

    dim3 grid(NPROP, NCH / CPB);
    crop_roi_kernel<<<grid, THREADS>>>(f, proposals, out);
}